// round 10
// baseline (speedup 1.0000x reference)
#include <cuda_runtime.h>
#include <cuda_bf16.h>
#include <cstdint>

#define NF 32
#define DIM 64
#define NPAIR 496
#define BATCH 2048
#define TILE_M 128
#define NTPB 2                        // batch tiles per CTA (pipelined)
#define LDSTR 72                      // bf16 elems per smem row (64 + 8 pad)
#define OSTR 72                       // floats per bounce row (R8 scheme)

// dynamic smem byte offsets
#define SM_W1H 0
#define SM_W1L 9216
#define SM_W2H 18432
#define SM_W2L 27648
#define SM_A0  36864                  // A buf0: AH at +0, AL at +18432 (36864 B)
#define SM_A1  73728                  // A buf1
#define SM_TOTAL 110592
#define A_HL_OFF 18432                // AL offset within an A buffer
// bounce aliases the active A buffer: 128 * 72 * 4 = 36864 B exactly

#define FE4 (BATCH * NF * DIM / 4)    // 1048576 float4 in fe

// ---- global bf16 hi/lo scratch (pre-split) ----
__device__ __align__(16) __nv_bfloat16 g_feH[BATCH * NF * DIM];
__device__ __align__(16) __nv_bfloat16 g_feL[BATCH * NF * DIM];
__device__ __align__(16) __nv_bfloat16 g_WH[NPAIR * DIM * DIM];
__device__ __align__(16) __nv_bfloat16 g_WL[NPAIR * DIM * DIM];

__device__ __forceinline__ uint32_t s2u(const void* p) {
    uint32_t a;
    asm("{ .reg .u64 t; cvta.to.shared.u64 t, %1; cvt.u32.u64 %0, t; }" : "=r"(a) : "l"(p));
    return a;
}
__device__ __forceinline__ void cpasync16(uint32_t s, const void* g) {
    asm volatile("{ .reg .u64 gp; cvta.to.global.u64 gp, %1; "
                 "cp.async.ca.shared.global [%0], [gp], 16; }"
                 :: "r"(s), "l"(g) : "memory");
}
__device__ __forceinline__ void ldsm_x4(uint32_t* r, uint32_t a) {
    asm volatile("ldmatrix.sync.aligned.m8n8.x4.shared.b16 {%0,%1,%2,%3}, [%4];"
                 : "=r"(r[0]), "=r"(r[1]), "=r"(r[2]), "=r"(r[3]) : "r"(a));
}
__device__ __forceinline__ void ldsm_x4t(uint32_t* r, uint32_t a) {
    asm volatile("ldmatrix.sync.aligned.m8n8.x4.trans.shared.b16 {%0,%1,%2,%3}, [%4];"
                 : "=r"(r[0]), "=r"(r[1]), "=r"(r[2]), "=r"(r[3]) : "r"(a));
}
__device__ __forceinline__ void mma_bf16(float* d, const uint32_t* a, const uint32_t* b) {
    asm volatile("mma.sync.aligned.m16n8k16.row.col.f32.bf16.bf16.f32 "
                 "{%0,%1,%2,%3}, {%4,%5,%6,%7}, {%8,%9}, {%0,%1,%2,%3};"
                 : "+f"(d[0]), "+f"(d[1]), "+f"(d[2]), "+f"(d[3])
                 : "r"(a[0]), "r"(a[1]), "r"(a[2]), "r"(a[3]), "r"(b[0]), "r"(b[1]));
}
__device__ __forceinline__ void split_bf16(float4 v, uint2& h, uint2& l) {
    __nv_bfloat16 hx = __float2bfloat16(v.x);
    __nv_bfloat16 hy = __float2bfloat16(v.y);
    __nv_bfloat16 hz = __float2bfloat16(v.z);
    __nv_bfloat16 hw = __float2bfloat16(v.w);
    __nv_bfloat162 h01 = __halves2bfloat162(hx, hy);
    __nv_bfloat162 h23 = __halves2bfloat162(hz, hw);
    __nv_bfloat162 l01 = __halves2bfloat162(
        __float2bfloat16(v.x - __bfloat162float(hx)),
        __float2bfloat16(v.y - __bfloat162float(hy)));
    __nv_bfloat162 l23 = __halves2bfloat162(
        __float2bfloat16(v.z - __bfloat162float(hz)),
        __float2bfloat16(v.w - __bfloat162float(hw)));
    h.x = *reinterpret_cast<uint32_t*>(&h01);
    h.y = *reinterpret_cast<uint32_t*>(&h23);
    l.x = *reinterpret_cast<uint32_t*>(&l01);
    l.y = *reinterpret_cast<uint32_t*>(&l23);
}

// ---- fused prep kernel: split fe and W fp32 -> bf16 hi/lo ----
__global__ __launch_bounds__(256) void split_all_kernel(
    const float* __restrict__ fe, const float* __restrict__ W) {
    int idx = blockIdx.x * 256 + threadIdx.x;
    if (idx < FE4) {
        float4 v = reinterpret_cast<const float4*>(fe)[idx];
        uint2 h, l; split_bf16(v, h, l);
        reinterpret_cast<uint2*>(g_feH)[idx] = h;
        reinterpret_cast<uint2*>(g_feL)[idx] = l;
    } else {
        int wi = idx - FE4;
        float4 v = reinterpret_cast<const float4*>(W)[wi];
        uint2 h, l; split_bf16(v, h, l);
        reinterpret_cast<uint2*>(g_WH)[wi] = h;
        reinterpret_cast<uint2*>(g_WL)[wi] = l;
    }
}

// pair index from (i, j): triu row-major
__device__ __forceinline__ int pair_idx(int i, int j) {
    return i * (2 * NF - i - 1) / 2 + (j - i - 1);
}

// out[b, p, e] = (sum_d fe[b, i(p), d] * W[p, d, e]) * fe[b, j(p), e]
__global__ __launch_bounds__(256, 2) void bilinear_mma_kernel(
    const float* __restrict__ fe,   // fp32, for v_j epilogue
    float* __restrict__ out)
{
    extern __shared__ char smem[];
    const uint32_t base = s2u(smem);
    const int tid = threadIdx.x;      // 0..255
    const int wid = tid >> 5;
    const int lid = tid & 31;
    const int g   = blockIdx.y;       // pair-group 0..255
    const int bt0 = blockIdx.x * NTPB;

    // decode group -> (i, j1, j2): duos 0..239, singles 240..255 (leftover j=31)
    int i, j1, j2;
    if (g < 240) {
        int rem = g; i = 0;
        while (rem >= ((NF - 1 - i) >> 1)) { rem -= (NF - 1 - i) >> 1; ++i; }
        j1 = i + 1 + 2 * rem; j2 = j1 + 1;
    } else {
        i = 2 * (g - 240); j1 = NF - 1; j2 = -1;
    }
    const int p1 = pair_idx(i, j1);
    const int p2 = (j2 >= 0) ? pair_idx(i, j2) : 0;

    // ---- W load (once per CTA) ----
    {
        #pragma unroll
        for (int q = 0; q < 2; ++q) {
            int chunk = tid + 256 * q;                    // 0..511
            int row = chunk >> 3, c = chunk & 7;
            const uint32_t sh = (uint32_t)(row * (LDSTR * 2) + c * 16);
            const size_t gb1 = (size_t)p1 * DIM * DIM + row * DIM + c * 8;
            cpasync16(base + SM_W1H + sh, g_WH + gb1);
            cpasync16(base + SM_W1L + sh, g_WL + gb1);
            if (j2 >= 0) {
                const size_t gb2 = (size_t)p2 * DIM * DIM + row * DIM + c * 8;
                cpasync16(base + SM_W2H + sh, g_WH + gb2);
                cpasync16(base + SM_W2L + sh, g_WL + gb2);
            }
        }
    }
    // ---- A tile loader ----
    auto loadA = [&](int bt, uint32_t abuf) {
        #pragma unroll
        for (int q = 0; q < 4; ++q) {
            int chunk = tid + 256 * q;                    // 0..1023
            int row = chunk >> 3, c = chunk & 7;
            const size_t gb = ((size_t)(bt * TILE_M + row) * NF + i) * DIM + c * 8;
            const uint32_t sh = (uint32_t)(row * (LDSTR * 2) + c * 16);
            cpasync16(abuf + sh, g_feH + gb);
            cpasync16(abuf + A_HL_OFF + sh, g_feL + gb);
        }
    };
    loadA(bt0, base + SM_A0);
    asm volatile("cp.async.commit_group;" ::: "memory");
    asm volatile("cp.async.wait_group 0;" ::: "memory");
    __syncthreads();

    // ---- warp tile: 32 (m) x 32 (n); 4x2 warp grid ----
    const int MR = (wid & 3) * 32;
    const int NC = (wid >> 2) * 32;
    const int lr = lid & 15, lc = lid >> 4;
    const uint32_t aW1h = base + SM_W1H + (uint32_t)lr * (LDSTR * 2) + NC * 2 + lc * 16;
    const int r  = lid >> 2;
    const int cp = (lid & 3) * 2;
    const int lane8 = tid & 7;

    #pragma unroll
    for (int t = 0; t < NTPB; ++t) {
        const uint32_t abuf = base + ((t & 1) ? SM_A1 : SM_A0);
        const int btile = bt0 + t;

        const uint32_t aAh0 = abuf + (uint32_t)(MR + lr) * (LDSTR * 2) + lc * 16;
        const uint32_t aAh1 = aAh0 + 16 * (LDSTR * 2);
        const uint32_t aAl0 = aAh0 + A_HL_OFF;
        const uint32_t aAl1 = aAh1 + A_HL_OFF;

        float acc1[2][4][4] = {};
        float acc2[2][4][4] = {};

        #pragma unroll
        for (int ks = 0; ks < 4; ++ks) {
            const uint32_t kA = (uint32_t)(ks * 32);
            const uint32_t kB = (uint32_t)(ks * 16 * (LDSTR * 2));

            uint32_t ah[2][4], al[2][4];
            ldsm_x4(ah[0], aAh0 + kA);
            ldsm_x4(ah[1], aAh1 + kA);
            ldsm_x4(al[0], aAl0 + kA);
            ldsm_x4(al[1], aAl1 + kA);

            // pair 1
            {
                uint32_t wh[8], wl[8];
                ldsm_x4t(wh,     aW1h + kB);
                ldsm_x4t(wh + 4, aW1h + kB + 32);
                ldsm_x4t(wl,     aW1h + (SM_W1L - SM_W1H) + kB);
                ldsm_x4t(wl + 4, aW1h + (SM_W1L - SM_W1H) + kB + 32);
                #pragma unroll
                for (int mi = 0; mi < 2; ++mi)
                    #pragma unroll
                    for (int ni = 0; ni < 4; ++ni) {
                        mma_bf16(acc1[mi][ni], ah[mi], &wh[ni * 2]);
                        mma_bf16(acc1[mi][ni], ah[mi], &wl[ni * 2]);
                        mma_bf16(acc1[mi][ni], al[mi], &wh[ni * 2]);
                    }
            }
            // pair 2
            if (j2 >= 0) {
                uint32_t wh[8], wl[8];
                ldsm_x4t(wh,     aW1h + (SM_W2H - SM_W1H) + kB);
                ldsm_x4t(wh + 4, aW1h + (SM_W2H - SM_W1H) + kB + 32);
                ldsm_x4t(wl,     aW1h + (SM_W2L - SM_W1H) + kB);
                ldsm_x4t(wl + 4, aW1h + (SM_W2L - SM_W1H) + kB + 32);
                #pragma unroll
                for (int mi = 0; mi < 2; ++mi)
                    #pragma unroll
                    for (int ni = 0; ni < 4; ++ni) {
                        mma_bf16(acc2[mi][ni], ah[mi], &wh[ni * 2]);
                        mma_bf16(acc2[mi][ni], ah[mi], &wl[ni * 2]);
                        mma_bf16(acc2[mi][ni], al[mi], &wh[ni * 2]);
                    }
            }
        }

        __syncthreads();   // all LDSM reads of this A buffer complete

        // prefetch next A tile into the other buffer (overlaps epilogue)
        if (t + 1 < NTPB) {
            loadA(bt0 + t + 1, base + (((t + 1) & 1) ? SM_A1 : SM_A0));
            asm volatile("cp.async.commit_group;" ::: "memory");
        }

        // ---- epilogue (R8 scheme): bounce through just-read A buffer ----
        float* bounce = reinterpret_cast<float*>(smem + ((t & 1) ? SM_A1 : SM_A0));
        #pragma unroll
        for (int pp = 0; pp < 2; ++pp) {
            if (pp == 1 && j2 < 0) break;
            const int jj = pp ? j2 : j1;
            const int pq = pp ? p2 : p1;
            float (*acc)[4][4] = pp ? acc2 : acc1;

            if (pp == 1) __syncthreads();   // prior reads of bounce complete
            #pragma unroll
            for (int mi = 0; mi < 2; ++mi)
                #pragma unroll
                for (int h = 0; h < 2; ++h) {
                    const int row = MR + mi * 16 + h * 8 + r;
                    #pragma unroll
                    for (int ni = 0; ni < 4; ++ni) {
                        const int col = NC + ni * 8 + cp;
                        *reinterpret_cast<float2*>(bounce + row * OSTR + col) =
                            make_float2(acc[mi][ni][h * 2 + 0], acc[mi][ni][h * 2 + 1]);
                    }
                }
            __syncthreads();

            #pragma unroll
            for (int rr = 0; rr < 4; ++rr) {
                const int row = rr * 32 + (tid >> 3);
                const int b = btile * TILE_M + row;
                const float* vjr = fe + ((size_t)b * NF + jj) * DIM;
                float* orow = out + ((size_t)b * NPAIR + pq) * DIM;
                #pragma unroll
                for (int h = 0; h < 2; ++h) {
                    const int col = lane8 * 4 + 32 * h;
                    float4 a4 = *reinterpret_cast<const float4*>(bounce + row * OSTR + col);
                    float4 vj = *reinterpret_cast<const float4*>(vjr + col);
                    float4 o;
                    o.x = a4.x * vj.x; o.y = a4.y * vj.y;
                    o.z = a4.z * vj.z; o.w = a4.w * vj.w;
                    *reinterpret_cast<float4*>(orow + col) = o;
                }
            }
        }

        if (t + 1 < NTPB) {
            asm volatile("cp.async.wait_group 0;" ::: "memory");
            __syncthreads();   // next A tile visible to all; bounce reads done
        }
    }
}

extern "C" void kernel_launch(void* const* d_in, const int* in_sizes, int n_in,
                              void* d_out, int out_size) {
    const float* fe = (const float*)d_in[0];   // feature_emb [2048, 32, 64] fp32
    const float* W  = (const float*)d_in[1];   // bilinear_W [496, 64, 64] fp32
    float* out = (float*)d_out;                // [2048, 496, 64] fp32

    const int n4 = FE4 + NPAIR * DIM * DIM / 4;     // 1556480 float4 total
    split_all_kernel<<<(n4 + 255) / 256, 256>>>(fe, W);

    cudaFuncSetAttribute(bilinear_mma_kernel,
                         cudaFuncAttributeMaxDynamicSharedMemorySize, SM_TOTAL);
    dim3 grid(BATCH / TILE_M / NTPB, 256);     // (8, 256)
    bilinear_mma_kernel<<<grid, 256, SM_TOTAL>>>(fe, out);
}

// round 11
// speedup vs baseline: 1.4201x; 1.4201x over previous
#include <cuda_runtime.h>
#include <cuda_fp16.h>
#include <cstdint>

#define NF 32
#define DIM 64
#define NPAIR 496
#define BATCH 2048
#define TILE_M 128
#define LDSTR 72                      // fp16 elems per smem row (64 + 8 pad)
#define OSTR 72                       // floats per bounce row

// smem layout: A [0, 18432), W [18432, 27648); bounce aliases [0, 36864)
#define SM_A 0
#define SM_W 18432
#define SM_TOTAL 36864

#define FE4 (BATCH * NF * DIM / 4)    // 1048576 float4 in fe

// ---- global fp16 scratch (pre-converted) ----
__device__ __align__(16) __half g_feF[BATCH * NF * DIM];
__device__ __align__(16) __half g_WF[NPAIR * DIM * DIM];

__device__ __forceinline__ uint32_t s2u(const void* p) {
    uint32_t a;
    asm("{ .reg .u64 t; cvta.to.shared.u64 t, %1; cvt.u32.u64 %0, t; }" : "=r"(a) : "l"(p));
    return a;
}
__device__ __forceinline__ void cpasync16(uint32_t s, const void* g) {
    asm volatile("{ .reg .u64 gp; cvta.to.global.u64 gp, %1; "
                 "cp.async.ca.shared.global [%0], [gp], 16; }"
                 :: "r"(s), "l"(g) : "memory");
}
__device__ __forceinline__ void ldsm_x4(uint32_t* r, uint32_t a) {
    asm volatile("ldmatrix.sync.aligned.m8n8.x4.shared.b16 {%0,%1,%2,%3}, [%4];"
                 : "=r"(r[0]), "=r"(r[1]), "=r"(r[2]), "=r"(r[3]) : "r"(a));
}
__device__ __forceinline__ void ldsm_x4t(uint32_t* r, uint32_t a) {
    asm volatile("ldmatrix.sync.aligned.m8n8.x4.trans.shared.b16 {%0,%1,%2,%3}, [%4];"
                 : "=r"(r[0]), "=r"(r[1]), "=r"(r[2]), "=r"(r[3]) : "r"(a));
}
__device__ __forceinline__ void mma_f16(float* d, const uint32_t* a, const uint32_t* b) {
    asm volatile("mma.sync.aligned.m16n8k16.row.col.f32.f16.f16.f32 "
                 "{%0,%1,%2,%3}, {%4,%5,%6,%7}, {%8,%9}, {%0,%1,%2,%3};"
                 : "+f"(d[0]), "+f"(d[1]), "+f"(d[2]), "+f"(d[3])
                 : "r"(a[0]), "r"(a[1]), "r"(a[2]), "r"(a[3]), "r"(b[0]), "r"(b[1]));
}

// ---- fused prep kernel: fp32 -> fp16 ----
__global__ __launch_bounds__(256) void cvt_all_kernel(
    const float* __restrict__ fe, const float* __restrict__ W) {
    int idx = blockIdx.x * 256 + threadIdx.x;
    float4 v;
    __half2* dst;
    if (idx < FE4) {
        v = reinterpret_cast<const float4*>(fe)[idx];
        dst = reinterpret_cast<__half2*>(g_feF) + idx * 2;
    } else {
        v = reinterpret_cast<const float4*>(W)[idx - FE4];
        dst = reinterpret_cast<__half2*>(g_WF) + (idx - FE4) * 2;
    }
    dst[0] = __floats2half2_rn(v.x, v.y);
    dst[1] = __floats2half2_rn(v.z, v.w);
}

// out[b, p, e] = (sum_d fe[b, i(p), d] * W[p, d, e]) * fe[b, j(p), e]
__global__ __launch_bounds__(256, 3) void bilinear_mma_kernel(
    const float* __restrict__ fe,   // fp32, for v_j epilogue
    float* __restrict__ out)
{
    extern __shared__ char smem[];
    const uint32_t base = s2u(smem);
    const int tid   = threadIdx.x;      // 0..255
    const int wid   = tid >> 5;
    const int lid   = tid & 31;
    const int p     = blockIdx.y;       // pair 0..495
    const int btile = blockIdx.x;

    // decode (i, j) from triu_indices(NF, k=1)
    int i = 0, rem = p;
    while (rem >= NF - 1 - i) { rem -= NF - 1 - i; ++i; }
    const int j = i + 1 + rem;

    // ---- async loads (fp16) ----
    // W: 64 rows x 64 fp16 = 512 x 16B chunks, 2/thread
    {
        #pragma unroll
        for (int q = 0; q < 2; ++q) {
            int chunk = tid + 256 * q;                    // 0..511
            int row = chunk >> 3, c = chunk & 7;
            const size_t gb = (size_t)p * DIM * DIM + row * DIM + c * 8;
            cpasync16(base + SM_W + (uint32_t)(row * (LDSTR * 2) + c * 16), g_WF + gb);
        }
    }
    // A: 128 rows x 64 fp16 = 1024 chunks, 4/thread
    {
        #pragma unroll
        for (int q = 0; q < 4; ++q) {
            int chunk = tid + 256 * q;                    // 0..1023
            int row = chunk >> 3, c = chunk & 7;
            const size_t gb = ((size_t)(btile * TILE_M + row) * NF + i) * DIM + c * 8;
            cpasync16(base + SM_A + (uint32_t)(row * (LDSTR * 2) + c * 16), g_feF + gb);
        }
    }
    asm volatile("cp.async.commit_group;" ::: "memory");
    asm volatile("cp.async.wait_group 0;" ::: "memory");
    __syncthreads();

    // ---- warp tile: 32 (m) x 32 (n); 4x2 warp grid (R4 schedule) ----
    const int MR = (wid & 3) * 32;
    const int NC = (wid >> 2) * 32;
    const int lr = lid & 15, lc = lid >> 4;

    const uint32_t aA0 = base + SM_A + (uint32_t)(MR + lr) * (LDSTR * 2) + lc * 16;
    const uint32_t aA1 = aA0 + 16 * (LDSTR * 2);
    const uint32_t aW  = base + SM_W + (uint32_t)lr * (LDSTR * 2) + NC * 2 + lc * 16;

    float acc[2][4][4] = {};

    #pragma unroll
    for (int ks = 0; ks < 4; ++ks) {
        const uint32_t kA = (uint32_t)(ks * 32);               // +16 k-cols (bytes)
        const uint32_t kB = (uint32_t)(ks * 16 * (LDSTR * 2)); // +16 k-rows (bytes)

        uint32_t af[2][4], wf[8];
        ldsm_x4(af[0], aA0 + kA);
        ldsm_x4(af[1], aA1 + kA);
        ldsm_x4t(wf,     aW + kB);
        ldsm_x4t(wf + 4, aW + kB + 32);

        #pragma unroll
        for (int mi = 0; mi < 2; ++mi)
            #pragma unroll
            for (int ni = 0; ni < 4; ++ni)
                mma_f16(acc[mi][ni], af[mi], &wf[ni * 2]);
    }

    // ---- epilogue: smem bounce -> coalesced vj-scale + store (R7 scheme) ----
    __syncthreads();   // all LDSM reads done; smem becomes bounce buffer
    float* bounce = reinterpret_cast<float*>(smem);

    const int r  = lid >> 2;
    const int cp = (lid & 3) * 2;
    #pragma unroll
    for (int mi = 0; mi < 2; ++mi)
        #pragma unroll
        for (int h = 0; h < 2; ++h) {
            const int row = MR + mi * 16 + h * 8 + r;
            #pragma unroll
            for (int ni = 0; ni < 4; ++ni) {
                const int col = NC + ni * 8 + cp;
                *reinterpret_cast<float2*>(bounce + row * OSTR + col) =
                    make_float2(acc[mi][ni][h * 2 + 0], acc[mi][ni][h * 2 + 1]);
            }
        }
    __syncthreads();

    const int lane8 = tid & 7;
    #pragma unroll
    for (int rr = 0; rr < 4; ++rr) {
        const int row = rr * 32 + (tid >> 3);
        const int b = btile * TILE_M + row;
        const float* vjr = fe + ((size_t)b * NF + j) * DIM;
        float* orow = out + ((size_t)b * NPAIR + p) * DIM;
        #pragma unroll
        for (int h = 0; h < 2; ++h) {
            const int col = lane8 * 4 + 32 * h;
            float4 a4 = *reinterpret_cast<const float4*>(bounce + row * OSTR + col);
            float4 vj = *reinterpret_cast<const float4*>(vjr + col);
            float4 o;
            o.x = a4.x * vj.x; o.y = a4.y * vj.y;
            o.z = a4.z * vj.z; o.w = a4.w * vj.w;
            *reinterpret_cast<float4*>(orow + col) = o;
        }
    }
}

extern "C" void kernel_launch(void* const* d_in, const int* in_sizes, int n_in,
                              void* d_out, int out_size) {
    const float* fe = (const float*)d_in[0];   // feature_emb [2048, 32, 64] fp32
    const float* W  = (const float*)d_in[1];   // bilinear_W [496, 64, 64] fp32
    float* out = (float*)d_out;                // [2048, 496, 64] fp32

    const int n4 = FE4 + NPAIR * DIM * DIM / 4;     // 1556480 float4 total
    cvt_all_kernel<<<(n4 + 255) / 256, 256>>>(fe, W);

    cudaFuncSetAttribute(bilinear_mma_kernel,
                         cudaFuncAttributeMaxDynamicSharedMemorySize, SM_TOTAL);
    dim3 grid(BATCH / TILE_M, NPAIR);          // (16, 496)
    bilinear_mma_kernel<<<grid, 256, SM_TOTAL>>>(fe, out);
}